// round 1
// baseline (speedup 1.0000x reference)
#include <cuda_runtime.h>

// Problem constants (fixed shapes from reference)
#define GX 432
#define GY 496
#define GZ 1
#define NVOX (GX * GY * GZ)        // 214272
#define MAXV 160000
#define B 4
#define NPER 200000
#define NPTS (B * NPER)            // 800000
#define ITEMS 2048                 // voxels per scan block (256 thr * 8)
#define NB ((NVOX + ITEMS - 1) / ITEMS)  // 105

__device__ int    g_count[NVOX];
__device__ float4 g_sum[NVOX];
__device__ int    g_bsum[NB];
__device__ int    g_boff[NB];

// ---------------------------------------------------------------------------
// Zero scratch + output
// ---------------------------------------------------------------------------
__global__ void zero_kernel(float4* __restrict__ out) {
    int i = blockIdx.x * blockDim.x + threadIdx.x;
    int stride = gridDim.x * blockDim.x;
    for (int v = i; v < NVOX; v += stride) {
        g_count[v] = 0;
        g_sum[v] = make_float4(0.f, 0.f, 0.f, 0.f);
    }
    for (int v = i; v < MAXV; v += stride)
        out[v] = make_float4(0.f, 0.f, 0.f, 0.f);
}

// ---------------------------------------------------------------------------
// Per-point scatter: count + feature sums via L2 reductions
// ---------------------------------------------------------------------------
__global__ void accum_kernel(const float* __restrict__ clouds) {
    int p = blockIdx.x * blockDim.x + threadIdx.x;
    if (p >= NPTS) return;
    int b = p / NPER;
    int n = p - b * NPER;
    const float* base = clouds + (size_t)b * 4 * NPER;
    float x = base[n];
    float y = base[NPER + n];
    float z = base[2 * NPER + n];
    float w = base[3 * NPER + n];

    // IEEE-correct divide regardless of --use_fast_math (matches XLA exactly)
    int cx = (int)floorf(__fdiv_rn(x - 0.0f,     0.16f));
    int cy = (int)floorf(__fdiv_rn(y - (-39.68f), 0.16f));
    int cz = (int)floorf(__fdiv_rn(z - (-3.0f),   4.0f));
    if (cx < 0 || cx >= GX || cy < 0 || cy >= GY || cz < 0 || cz >= GZ) return;

    int lin = (cz * GY + cy) * GX + cx;

    atomicAdd(&g_count[lin], 1);   // compiles to RED.E.ADD (no return use)
    float* s = &g_sum[lin].x;
    asm volatile("red.global.add.v2.f32 [%0], {%1, %2};"
                 :: "l"(s), "f"(x), "f"(y) : "memory");
    asm volatile("red.global.add.v2.f32 [%0], {%1, %2};"
                 :: "l"(s + 2), "f"(z), "f"(w) : "memory");
}

// ---------------------------------------------------------------------------
// Scan pass 1: per-block occupancy sums
// ---------------------------------------------------------------------------
__global__ void scan1_kernel() {
    __shared__ int sh[256];
    int tid = threadIdx.x;
    int base = blockIdx.x * ITEMS + tid * 8;
    int tsum = 0;
#pragma unroll
    for (int i = 0; i < 8; i++) {
        int v = base + i;
        if (v < NVOX && g_count[v] > 0) tsum++;
    }
    sh[tid] = tsum;
    __syncthreads();
    for (int off = 128; off > 0; off >>= 1) {
        if (tid < off) sh[tid] += sh[tid + off];
        __syncthreads();
    }
    if (tid == 0) g_bsum[blockIdx.x] = sh[0];
}

// ---------------------------------------------------------------------------
// Scan pass 2: exclusive scan of the 105 block sums (single block)
// ---------------------------------------------------------------------------
__global__ void scan2_kernel() {
    __shared__ int sh[128];
    int tid = threadIdx.x;
    int v = (tid < NB) ? g_bsum[tid] : 0;
    sh[tid] = v;
    __syncthreads();
    for (int off = 1; off < 128; off <<= 1) {
        int t = (tid >= off) ? sh[tid - off] : 0;
        __syncthreads();
        sh[tid] += t;
        __syncthreads();
    }
    if (tid < NB) g_boff[tid] = sh[tid] - v;  // exclusive prefix
}

// ---------------------------------------------------------------------------
// Scan pass 3: local exclusive scan + emit means into output rows
// ---------------------------------------------------------------------------
__global__ void scan3_kernel(float4* __restrict__ out) {
    __shared__ int sh[256];
    int tid = threadIdx.x;
    int base = blockIdx.x * ITEMS + tid * 8;
    int occ[8];
    int tsum = 0;
#pragma unroll
    for (int i = 0; i < 8; i++) {
        int v = base + i;
        occ[i] = (v < NVOX && g_count[v] > 0) ? 1 : 0;
        tsum += occ[i];
    }
    sh[tid] = tsum;
    __syncthreads();
    int run = tsum;
    for (int off = 1; off < 256; off <<= 1) {
        int t = (tid >= off) ? sh[tid - off] : 0;
        __syncthreads();
        run += t;
        sh[tid] = run;
        __syncthreads();
    }
    int rank = g_boff[blockIdx.x] + (run - tsum);  // exclusive within grid
#pragma unroll
    for (int i = 0; i < 8; i++) {
        if (occ[i]) {
            if (rank < MAXV) {
                int v = base + i;
                float cnt = (float)g_count[v];
                float4 s = g_sum[v];
                out[rank] = make_float4(s.x / cnt, s.y / cnt, s.z / cnt, s.w / cnt);
            }
            rank++;
        }
    }
}

// ---------------------------------------------------------------------------
extern "C" void kernel_launch(void* const* d_in, const int* in_sizes, int n_in,
                              void* d_out, int out_size) {
    const float* clouds = (const float*)d_in[0];
    float4* out = (float4*)d_out;

    zero_kernel<<<264, 256>>>(out);
    accum_kernel<<<(NPTS + 255) / 256, 256>>>(clouds);
    scan1_kernel<<<NB, 256>>>();
    scan2_kernel<<<1, 128>>>();
    scan3_kernel<<<NB, 256>>>(out);
}